// round 6
// baseline (speedup 1.0000x reference)
#include <cuda_runtime.h>
#include <math_constants.h>

#define SDIM 2048
#define BDIM 32
#define HDIM 1024

#define KS 16          // k-splits
#define KT (HDIM / KS) // 64 k per split
#define HT 128         // h per block tile (8 tiles)

// Scratch (no device allocs allowed). Counter self-resets -> graph-replayable.
__device__ float g_part[KS * BDIM * HDIM];      // split-K partials (2 MB)
__device__ float g_u[BDIM * HDIM];              // u = hidden @ W
__device__ float g_scores[BDIM * SDIM];         // scores[b,s]
__device__ unsigned int g_pcount[HDIM / HT];    // proj k-splits-done per h-tile

// ---------------------------------------------------------------------------
// Kernel 1: split-K tiled GEMM u = hidden @ W, last-block-per-h-tile fold.
// grid = (8 h-tiles, 16 k-splits) = 128 blocks, 256 threads.
// ---------------------------------------------------------------------------
__global__ __launch_bounds__(256) void proj_kernel(
    const float* __restrict__ hidden, const float* __restrict__ W) {
    __shared__ float4 sW[KT * (HT / 4)];   // 32 KB
    __shared__ float  sH[BDIM * KT];       // 8 KB
    __shared__ bool amLast;

    const int h0 = blockIdx.x * HT;
    const int k0 = blockIdx.y * KT;
    const int tid = threadIdx.x;

    const float4* __restrict__ Wg = reinterpret_cast<const float4*>(W);
#pragma unroll
    for (int i = 0; i < (KT * HT / 4) / 256; ++i) {
        int idx = tid + i * 256;
        int kk = idx >> 5;
        int c  = idx & 31;
        sW[idx] = Wg[(size_t)(k0 + kk) * (HDIM / 4) + (h0 >> 2) + c];
    }
#pragma unroll
    for (int i = 0; i < (BDIM * KT) / 256; ++i) {
        int idx = tid + i * 256;
        int bb = idx >> 6;
        int kk = idx & 63;
        sH[idx] = hidden[bb * HDIM + k0 + kk];
    }
    __syncthreads();

    const int lane = tid & 31;
    const int b0 = (tid >> 5) * 4;

    float4 acc0 = {0,0,0,0}, acc1 = {0,0,0,0}, acc2 = {0,0,0,0}, acc3 = {0,0,0,0};
#pragma unroll 8
    for (int k = 0; k < KT; ++k) {
        float4 w4 = sW[k * 32 + lane];
        float h0v = sH[(b0 + 0) * KT + k];
        float h1v = sH[(b0 + 1) * KT + k];
        float h2v = sH[(b0 + 2) * KT + k];
        float h3v = sH[(b0 + 3) * KT + k];
        acc0.x = fmaf(h0v, w4.x, acc0.x); acc0.y = fmaf(h0v, w4.y, acc0.y);
        acc0.z = fmaf(h0v, w4.z, acc0.z); acc0.w = fmaf(h0v, w4.w, acc0.w);
        acc1.x = fmaf(h1v, w4.x, acc1.x); acc1.y = fmaf(h1v, w4.y, acc1.y);
        acc1.z = fmaf(h1v, w4.z, acc1.z); acc1.w = fmaf(h1v, w4.w, acc1.w);
        acc2.x = fmaf(h2v, w4.x, acc2.x); acc2.y = fmaf(h2v, w4.y, acc2.y);
        acc2.z = fmaf(h2v, w4.z, acc2.z); acc2.w = fmaf(h2v, w4.w, acc2.w);
        acc3.x = fmaf(h3v, w4.x, acc3.x); acc3.y = fmaf(h3v, w4.y, acc3.y);
        acc3.z = fmaf(h3v, w4.z, acc3.z); acc3.w = fmaf(h3v, w4.w, acc3.w);
    }

    float4* __restrict__ part4 = reinterpret_cast<float4*>(
        g_part + (size_t)blockIdx.y * BDIM * HDIM);
    const int hbase4 = (h0 >> 2) + lane;
    part4[(b0 + 0) * (HDIM / 4) + hbase4] = acc0;
    part4[(b0 + 1) * (HDIM / 4) + hbase4] = acc1;
    part4[(b0 + 2) * (HDIM / 4) + hbase4] = acc2;
    part4[(b0 + 3) * (HDIM / 4) + hbase4] = acc3;

    // ---- last k-split block for this h-tile folds partials into g_u ----
    __threadfence();
    if (tid == 0) {
        unsigned int old = atomicAdd(&g_pcount[blockIdx.x], 1u);
        amLast = (old == KS - 1);
        if (amLast) g_pcount[blockIdx.x] = 0u;   // self-reset for next replay
    }
    __syncthreads();
    if (amLast) {
        __threadfence();
        for (int i = tid; i < BDIM * (HT / 4); i += 256) {   // 4 iters
            int bb = i >> 5;
            int c  = i & 31;
            float4 s = {0, 0, 0, 0};
#pragma unroll
            for (int j = 0; j < KS; ++j) {
                float4 p = *reinterpret_cast<const float4*>(
                    g_part + (size_t)j * BDIM * HDIM + bb * HDIM + h0 + 4 * c);
                s.x += p.x; s.y += p.y; s.z += p.z; s.w += p.w;
            }
            *reinterpret_cast<float4*>(g_u + bb * HDIM + h0 + 4 * c) = s;
        }
    }
}

// ---------------------------------------------------------------------------
// Kernel 2: scores[b,s] = u[b] . enc[s,b,:] — pure 268 MB HBM stream (R3 form:
// no atomics, no tail work; this ran at ~82% of HBM spec).
// ---------------------------------------------------------------------------
__global__ __launch_bounds__(256) void score_kernel(const float* __restrict__ enc) {
    const int warp = (blockIdx.x * blockDim.x + threadIdx.x) >> 5;
    const int lane = threadIdx.x & 31;
    if (warp >= SDIM * BDIM) return;

    const int b = warp & (BDIM - 1);
    const int s = warp >> 5;

    const float4* __restrict__ erow =
        reinterpret_cast<const float4*>(enc + (size_t)warp * HDIM);
    const float4* __restrict__ urow =
        reinterpret_cast<const float4*>(g_u + b * HDIM);

    float acc = 0.0f;
#pragma unroll
    for (int j = 0; j < 8; ++j) {
        float4 e = __ldcs(&erow[j * 32 + lane]);   // streaming, evict-first
        float4 u = __ldg(&urow[j * 32 + lane]);    // cached, L2-resident
        acc = fmaf(e.x, u.x, acc);
        acc = fmaf(e.y, u.y, acc);
        acc = fmaf(e.z, u.z, acc);
        acc = fmaf(e.w, u.w, acc);
    }
#pragma unroll
    for (int off = 16; off > 0; off >>= 1)
        acc += __shfl_xor_sync(0xFFFFFFFFu, acc, off);

    if (lane == 0) g_scores[b * SDIM + s] = acc;
}

// ---------------------------------------------------------------------------
// Kernel 3: softmax over s per b. 32 blocks x 1024 threads (R3 form).
// ---------------------------------------------------------------------------
__global__ __launch_bounds__(1024) void softmax_kernel(float* __restrict__ out) {
    const int b = blockIdx.x;
    const int tid = threadIdx.x;
    const float* __restrict__ row = g_scores + b * SDIM;

    __shared__ float sred[32];

    float v0 = row[tid];
    float v1 = row[tid + 1024];
    float vmax = fmaxf(v0, v1);
#pragma unroll
    for (int off = 16; off > 0; off >>= 1)
        vmax = fmaxf(vmax, __shfl_xor_sync(0xFFFFFFFFu, vmax, off));
    if ((tid & 31) == 0) sred[tid >> 5] = vmax;
    __syncthreads();
    if (tid < 32) {
        float v = sred[tid];
#pragma unroll
        for (int off = 16; off > 0; off >>= 1)
            v = fmaxf(v, __shfl_xor_sync(0xFFFFFFFFu, v, off));
        sred[0] = v;
    }
    __syncthreads();
    vmax = sred[0];
    __syncthreads();

    v0 = __expf(v0 - vmax);
    v1 = __expf(v1 - vmax);
    float lsum = v0 + v1;
#pragma unroll
    for (int off = 16; off > 0; off >>= 1)
        lsum += __shfl_xor_sync(0xFFFFFFFFu, lsum, off);
    if ((tid & 31) == 0) sred[tid >> 5] = lsum;
    __syncthreads();
    if (tid < 32) {
        float v = sred[tid];
#pragma unroll
        for (int off = 16; off > 0; off >>= 1)
            v += __shfl_xor_sync(0xFFFFFFFFu, v, off);
        sred[0] = v;
    }
    __syncthreads();
    const float inv = 1.0f / sred[0];

    out[b * SDIM + tid]        = v0 * inv;
    out[b * SDIM + tid + 1024] = v1 * inv;
}

// ---------------------------------------------------------------------------
extern "C" void kernel_launch(void* const* d_in, const int* in_sizes, int n_in,
                              void* d_out, int out_size) {
    const float* hidden = (const float*)d_in[0];  // [B,H]
    const float* enc    = (const float*)d_in[1];  // [S,B,H]
    const float* W      = (const float*)d_in[2];  // [H,H]
    float* out = (float*)d_out;                   // [1,B,S]

    dim3 pg(HDIM / HT, KS);                       // (8, 16)
    proj_kernel<<<pg, 256>>>(hidden, W);

    const int total_warps = SDIM * BDIM;          // 65536
    score_kernel<<<total_warps * 32 / 256, 256>>>(enc);

    softmax_kernel<<<BDIM, 1024>>>(out);
}

// round 7
// speedup vs baseline: 1.0719x; 1.0719x over previous
#include <cuda_runtime.h>
#include <math_constants.h>

#define SDIM 2048
#define BDIM 32
#define HDIM 1024

#define KS 16          // k-splits
#define KT (HDIM / KS) // 64 k per split
#define HT 128         // h per block tile (8 tiles)
#define NRED 128       // reducer blocks inside score_kernel

// Scratch (no device allocs allowed)
__device__ float g_part[KS * BDIM * HDIM];      // split-K partials (2 MB)
__device__ float g_u[BDIM * HDIM];              // u = hidden @ W
__device__ float g_scores[BDIM * SDIM];         // scores[b,s]
__device__ unsigned int g_rcount;               // reducers-done counter (reset by softmax)

// ---------------------------------------------------------------------------
// Kernel 1: split-K tiled GEMM u_part = hidden[:, krange] @ W[krange, htile]
// Lean R2 form: grid (8 h-tiles, 16 k-splits) = 128 blocks, 256 threads.
// ---------------------------------------------------------------------------
__global__ __launch_bounds__(256) void proj_kernel(
    const float* __restrict__ hidden, const float* __restrict__ W) {
    __shared__ float4 sW[KT * (HT / 4)];   // 32 KB
    __shared__ float  sH[BDIM * KT];       // 8 KB

    const int h0 = blockIdx.x * HT;
    const int k0 = blockIdx.y * KT;
    const int tid = threadIdx.x;

    const float4* __restrict__ Wg = reinterpret_cast<const float4*>(W);
#pragma unroll
    for (int i = 0; i < (KT * HT / 4) / 256; ++i) {
        int idx = tid + i * 256;
        int kk = idx >> 5;
        int c  = idx & 31;
        sW[idx] = Wg[(size_t)(k0 + kk) * (HDIM / 4) + (h0 >> 2) + c];
    }
#pragma unroll
    for (int i = 0; i < (BDIM * KT) / 256; ++i) {
        int idx = tid + i * 256;
        int bb = idx >> 6;
        int kk = idx & 63;
        sH[idx] = hidden[bb * HDIM + k0 + kk];
    }
    __syncthreads();

    const int lane = tid & 31;
    const int b0 = (tid >> 5) * 4;

    float4 acc0 = {0,0,0,0}, acc1 = {0,0,0,0}, acc2 = {0,0,0,0}, acc3 = {0,0,0,0};
#pragma unroll 8
    for (int k = 0; k < KT; ++k) {
        float4 w4 = sW[k * 32 + lane];
        float h0v = sH[(b0 + 0) * KT + k];
        float h1v = sH[(b0 + 1) * KT + k];
        float h2v = sH[(b0 + 2) * KT + k];
        float h3v = sH[(b0 + 3) * KT + k];
        acc0.x = fmaf(h0v, w4.x, acc0.x); acc0.y = fmaf(h0v, w4.y, acc0.y);
        acc0.z = fmaf(h0v, w4.z, acc0.z); acc0.w = fmaf(h0v, w4.w, acc0.w);
        acc1.x = fmaf(h1v, w4.x, acc1.x); acc1.y = fmaf(h1v, w4.y, acc1.y);
        acc1.z = fmaf(h1v, w4.z, acc1.z); acc1.w = fmaf(h1v, w4.w, acc1.w);
        acc2.x = fmaf(h2v, w4.x, acc2.x); acc2.y = fmaf(h2v, w4.y, acc2.y);
        acc2.z = fmaf(h2v, w4.z, acc2.z); acc2.w = fmaf(h2v, w4.w, acc2.w);
        acc3.x = fmaf(h3v, w4.x, acc3.x); acc3.y = fmaf(h3v, w4.y, acc3.y);
        acc3.z = fmaf(h3v, w4.z, acc3.z); acc3.w = fmaf(h3v, w4.w, acc3.w);
    }

    float4* __restrict__ part4 = reinterpret_cast<float4*>(
        g_part + (size_t)blockIdx.y * BDIM * HDIM);
    const int hbase4 = (h0 >> 2) + lane;
    part4[(b0 + 0) * (HDIM / 4) + hbase4] = acc0;
    part4[(b0 + 1) * (HDIM / 4) + hbase4] = acc1;
    part4[(b0 + 2) * (HDIM / 4) + hbase4] = acc2;
    part4[(b0 + 3) * (HDIM / 4) + hbase4] = acc3;
}

// ---------------------------------------------------------------------------
// Kernel 2: reduce-prologue + scores[b,s] = u[b] . enc[s,b,:].
// Blocks 0..127 fold split-K partials (L2-hot, fixed order -> deterministic),
// then everyone streams. Inner loop identical to the proven ~41us version.
// ---------------------------------------------------------------------------
__global__ __launch_bounds__(256) void score_kernel(const float* __restrict__ enc) {
    const int bid = blockIdx.x;
    const int tid = threadIdx.x;

    // ---- prologue: fold g_part -> g_u (blocks 0..127, 64 float4 each) ----
    if (bid < NRED) {
        if (tid < 64) {
            const int idx4 = bid * 64 + tid;          // 0..8191 float4 of g_u
            float4 s4 = {0, 0, 0, 0};
#pragma unroll
            for (int j = 0; j < KS; ++j) {
                float4 p = *reinterpret_cast<const float4*>(
                    g_part + (size_t)j * BDIM * HDIM + 4 * idx4);
                s4.x += p.x; s4.y += p.y; s4.z += p.z; s4.w += p.w;
            }
            *reinterpret_cast<float4*>(g_u + 4 * idx4) = s4;
        }
        __threadfence();
        __syncthreads();
        if (tid == 0) atomicAdd(&g_rcount, 1u);
    }

    // ---- wait until all reducers done (thread 0 spins, short) ----
    if (tid == 0) {
        while (*((volatile unsigned int*)&g_rcount) < NRED) __nanosleep(64);
    }
    __syncthreads();
    __threadfence();   // acquire g_u

    // ---- streaming dot products (unchanged from the 41us version) ----
    const int warp = (bid * 256 + tid) >> 5;
    const int lane = tid & 31;
    const int b = warp & (BDIM - 1);
    const int s = warp >> 5;

    const float4* __restrict__ erow =
        reinterpret_cast<const float4*>(enc + (size_t)warp * HDIM);
    const float4* __restrict__ urow =
        reinterpret_cast<const float4*>(g_u + b * HDIM);

    float acc = 0.0f;
#pragma unroll
    for (int j = 0; j < 8; ++j) {
        float4 e = __ldcs(&erow[j * 32 + lane]);   // streaming, evict-first
        float4 u = __ldg(&urow[j * 32 + lane]);    // cached, L2-resident
        acc = fmaf(e.x, u.x, acc);
        acc = fmaf(e.y, u.y, acc);
        acc = fmaf(e.z, u.z, acc);
        acc = fmaf(e.w, u.w, acc);
    }
#pragma unroll
    for (int off = 16; off > 0; off >>= 1)
        acc += __shfl_xor_sync(0xFFFFFFFFu, acc, off);

    if (lane == 0) g_scores[b * SDIM + s] = acc;
}

// ---------------------------------------------------------------------------
// Kernel 3: softmax over s per b. 32 blocks x 1024 threads. Also resets
// g_rcount for the next graph replay (runs strictly after score_kernel).
// ---------------------------------------------------------------------------
__global__ __launch_bounds__(1024) void softmax_kernel(float* __restrict__ out) {
    const int b = blockIdx.x;
    const int tid = threadIdx.x;
    const float* __restrict__ row = g_scores + b * SDIM;

    if (b == 0 && tid == 0) g_rcount = 0u;   // reset for next replay

    __shared__ float sred[32];

    float v0 = row[tid];
    float v1 = row[tid + 1024];
    float vmax = fmaxf(v0, v1);
#pragma unroll
    for (int off = 16; off > 0; off >>= 1)
        vmax = fmaxf(vmax, __shfl_xor_sync(0xFFFFFFFFu, vmax, off));
    if ((tid & 31) == 0) sred[tid >> 5] = vmax;
    __syncthreads();
    if (tid < 32) {
        float v = sred[tid];
#pragma unroll
        for (int off = 16; off > 0; off >>= 1)
            v = fmaxf(v, __shfl_xor_sync(0xFFFFFFFFu, v, off));
        sred[0] = v;
    }
    __syncthreads();
    vmax = sred[0];
    __syncthreads();

    v0 = __expf(v0 - vmax);
    v1 = __expf(v1 - vmax);
    float lsum = v0 + v1;
#pragma unroll
    for (int off = 16; off > 0; off >>= 1)
        lsum += __shfl_xor_sync(0xFFFFFFFFu, lsum, off);
    if ((tid & 31) == 0) sred[tid >> 5] = lsum;
    __syncthreads();
    if (tid < 32) {
        float v = sred[tid];
#pragma unroll
        for (int off = 16; off > 0; off >>= 1)
            v += __shfl_xor_sync(0xFFFFFFFFu, v, off);
        sred[0] = v;
    }
    __syncthreads();
    const float inv = 1.0f / sred[0];

    out[b * SDIM + tid]        = v0 * inv;
    out[b * SDIM + tid + 1024] = v1 * inv;
}

// ---------------------------------------------------------------------------
extern "C" void kernel_launch(void* const* d_in, const int* in_sizes, int n_in,
                              void* d_out, int out_size) {
    const float* hidden = (const float*)d_in[0];  // [B,H]
    const float* enc    = (const float*)d_in[1];  // [S,B,H]
    const float* W      = (const float*)d_in[2];  // [H,H]
    float* out = (float*)d_out;                   // [1,B,S]

    dim3 pg(HDIM / HT, KS);                       // (8, 16)
    proj_kernel<<<pg, 256>>>(hidden, W);

    score_kernel<<<(SDIM * BDIM) / 8, 256>>>(enc);   // 8192 blocks

    softmax_kernel<<<BDIM, 1024>>>(out);
}

// round 8
// speedup vs baseline: 1.1986x; 1.1182x over previous
#include <cuda_runtime.h>
#include <math_constants.h>

#define SDIM 2048
#define BDIM 32
#define HDIM 1024

#define KS 16          // k-splits
#define KT (HDIM / KS) // 64 k per split
#define HT 128         // h per block tile (8 tiles)

// Scratch (no device allocs allowed)
__device__ float g_part[KS * BDIM * HDIM];  // split-K partials (2 MB)
__device__ float g_u[BDIM * HDIM];          // u = hidden @ W
__device__ float g_scores[BDIM * SDIM];     // scores[b,s]

// ---------------------------------------------------------------------------
// Kernel 1: split-K tiled GEMM u_part = hidden[:, krange] @ W[krange, htile]
// grid (8 h-tiles, 16 k-splits) = 128 blocks, 512 threads (16 warps/SM).
// Each thread: 2 b x 4 h outputs -> half the serial chain of the 256t version.
// ---------------------------------------------------------------------------
__global__ __launch_bounds__(512) void proj_kernel(
    const float* __restrict__ hidden, const float* __restrict__ W) {
    __shared__ float4 sW[KT * (HT / 4)];   // 64k x 32 float4 = 32 KB
    __shared__ float  sH[BDIM * KT];       // 32b x 64k       = 8 KB

    const int h0 = blockIdx.x * HT;
    const int k0 = blockIdx.y * KT;
    const int tid = threadIdx.x;

    const float4* __restrict__ Wg = reinterpret_cast<const float4*>(W);
#pragma unroll
    for (int i = 0; i < (KT * HT / 4) / 512; ++i) {   // 4 iters
        int idx = tid + i * 512;
        int kk = idx >> 5;
        int c  = idx & 31;
        sW[idx] = Wg[(size_t)(k0 + kk) * (HDIM / 4) + (h0 >> 2) + c];
    }
#pragma unroll
    for (int i = 0; i < (BDIM * KT) / 512; ++i) {     // 4 iters
        int idx = tid + i * 512;
        int bb = idx >> 6;
        int kk = idx & 63;
        sH[idx] = hidden[bb * HDIM + k0 + kk];
    }
    __syncthreads();

    const int lane = tid & 31;          // h4 index (128 h / 4)
    const int b0 = (tid >> 5) * 2;      // 16 warps x 2 b = 32 b

    float4 acc0 = {0,0,0,0}, acc1 = {0,0,0,0};
#pragma unroll 16
    for (int k = 0; k < KT; ++k) {
        float4 w4 = sW[k * 32 + lane];
        float h0v = sH[(b0 + 0) * KT + k];
        float h1v = sH[(b0 + 1) * KT + k];
        acc0.x = fmaf(h0v, w4.x, acc0.x); acc0.y = fmaf(h0v, w4.y, acc0.y);
        acc0.z = fmaf(h0v, w4.z, acc0.z); acc0.w = fmaf(h0v, w4.w, acc0.w);
        acc1.x = fmaf(h1v, w4.x, acc1.x); acc1.y = fmaf(h1v, w4.y, acc1.y);
        acc1.z = fmaf(h1v, w4.z, acc1.z); acc1.w = fmaf(h1v, w4.w, acc1.w);
    }

    float4* __restrict__ part4 = reinterpret_cast<float4*>(
        g_part + (size_t)blockIdx.y * BDIM * HDIM);
    const int hbase4 = (h0 >> 2) + lane;
    part4[(b0 + 0) * (HDIM / 4) + hbase4] = acc0;
    part4[(b0 + 1) * (HDIM / 4) + hbase4] = acc1;
}

// ---------------------------------------------------------------------------
// Kernel 1b: fold split-K partials (deterministic fixed order).
// __ldcs on g_part: read-once, keep L2 for g_u / the stream.
// ---------------------------------------------------------------------------
__global__ __launch_bounds__(256) void reduce_kernel() {
    const int idx4 = blockIdx.x * 256 + threadIdx.x;   // float4 index, 0..8191
    float4 s4 = {0, 0, 0, 0};
#pragma unroll
    for (int j = 0; j < KS; ++j) {
        float4 p = __ldcs(reinterpret_cast<const float4*>(
            g_part + (size_t)j * BDIM * HDIM) + idx4);
        s4.x += p.x; s4.y += p.y; s4.z += p.z; s4.w += p.w;
    }
    reinterpret_cast<float4*>(g_u)[idx4] = s4;
}

// ---------------------------------------------------------------------------
// Kernel 2: scores[b,s] = u[b] . enc[s,b,:] — pure 268 MB HBM stream.
// (Proven form: no atomics, no prologue, no tail.)
// ---------------------------------------------------------------------------
__global__ __launch_bounds__(256) void score_kernel(const float* __restrict__ enc) {
    const int warp = (blockIdx.x * blockDim.x + threadIdx.x) >> 5;
    const int lane = threadIdx.x & 31;
    if (warp >= SDIM * BDIM) return;

    const int b = warp & (BDIM - 1);
    const int s = warp >> 5;

    const float4* __restrict__ erow =
        reinterpret_cast<const float4*>(enc + (size_t)warp * HDIM);
    const float4* __restrict__ urow =
        reinterpret_cast<const float4*>(g_u + b * HDIM);

    float acc = 0.0f;
#pragma unroll
    for (int j = 0; j < 8; ++j) {
        float4 e = __ldcs(&erow[j * 32 + lane]);   // streaming, evict-first
        float4 u = __ldg(&urow[j * 32 + lane]);    // cached, L2-resident
        acc = fmaf(e.x, u.x, acc);
        acc = fmaf(e.y, u.y, acc);
        acc = fmaf(e.z, u.z, acc);
        acc = fmaf(e.w, u.w, acc);
    }
#pragma unroll
    for (int off = 16; off > 0; off >>= 1)
        acc += __shfl_xor_sync(0xFFFFFFFFu, acc, off);

    if (lane == 0) g_scores[b * SDIM + s] = acc;
}

// ---------------------------------------------------------------------------
// Kernel 3: softmax over s per b. 32 blocks x 1024 threads.
// ---------------------------------------------------------------------------
__global__ __launch_bounds__(1024) void softmax_kernel(float* __restrict__ out) {
    const int b = blockIdx.x;
    const int tid = threadIdx.x;
    const float* __restrict__ row = g_scores + b * SDIM;

    __shared__ float sred[32];

    float v0 = row[tid];
    float v1 = row[tid + 1024];
    float vmax = fmaxf(v0, v1);
#pragma unroll
    for (int off = 16; off > 0; off >>= 1)
        vmax = fmaxf(vmax, __shfl_xor_sync(0xFFFFFFFFu, vmax, off));
    if ((tid & 31) == 0) sred[tid >> 5] = vmax;
    __syncthreads();
    if (tid < 32) {
        float v = sred[tid];
#pragma unroll
        for (int off = 16; off > 0; off >>= 1)
            v = fmaxf(v, __shfl_xor_sync(0xFFFFFFFFu, v, off));
        sred[0] = v;
    }
    __syncthreads();
    vmax = sred[0];
    __syncthreads();

    v0 = __expf(v0 - vmax);
    v1 = __expf(v1 - vmax);
    float lsum = v0 + v1;
#pragma unroll
    for (int off = 16; off > 0; off >>= 1)
        lsum += __shfl_xor_sync(0xFFFFFFFFu, lsum, off);
    if ((tid & 31) == 0) sred[tid >> 5] = lsum;
    __syncthreads();
    if (tid < 32) {
        float v = sred[tid];
#pragma unroll
        for (int off = 16; off > 0; off >>= 1)
            v += __shfl_xor_sync(0xFFFFFFFFu, v, off);
        sred[0] = v;
    }
    __syncthreads();
    const float inv = 1.0f / sred[0];

    out[b * SDIM + tid]        = v0 * inv;
    out[b * SDIM + tid + 1024] = v1 * inv;
}

// ---------------------------------------------------------------------------
extern "C" void kernel_launch(void* const* d_in, const int* in_sizes, int n_in,
                              void* d_out, int out_size) {
    const float* hidden = (const float*)d_in[0];  // [B,H]
    const float* enc    = (const float*)d_in[1];  // [S,B,H]
    const float* W      = (const float*)d_in[2];  // [H,H]
    float* out = (float*)d_out;                   // [1,B,S]

    dim3 pg(HDIM / HT, KS);                       // (8, 16)
    proj_kernel<<<pg, 512>>>(hidden, W);
    reduce_kernel<<<(BDIM * HDIM / 4) / 256, 256>>>();   // 32 blocks

    const int total_warps = SDIM * BDIM;          // 65536
    score_kernel<<<total_warps * 32 / 256, 256>>>(enc);

    softmax_kernel<<<BDIM, 1024>>>(out);
}